// round 2
// baseline (speedup 1.0000x reference)
#include <cuda_runtime.h>
#include <math.h>

#define BB 4
#define CC 64
#define HH 96
#define WW 96
#define N0 (HH*WW)      // 9216
#define N1 (48*48)      // 2304
#define N2 (24*24)      // 576

// ------------- scratch (static device globals; no allocation) -------------
__device__ __align__(16) float g_xp [BB*CC*N0];
__device__ __align__(16) float g_s1 [BB*CC*N1];
__device__ __align__(16) float g_s2 [BB*CC*N2];
__device__ __align__(16) float g_qkv [BB*192*N0];
__device__ __align__(16) float g_qkv2[BB*192*N0];
__device__ __align__(16) float g_up1[BB*CC*N0];
__device__ __align__(16) float g_up2[BB*CC*N0];
__device__ __align__(16) float g_xre[BB*CC*N0];
__device__ __align__(16) float g_xr [BB*CC*N0];
__device__ __align__(16) float g_norms[BB*128];
__device__ __align__(16) float g_gram[BB*4*16*16];
__device__ __align__(16) float g_W2[BB*64*64];
__device__ __align__(16) float g_gnstat[BB*4*2];

__device__ __forceinline__ float siluf(float x){ return x / (1.f + expf(-x)); }

__device__ __forceinline__ float* buf_ptr(int sel){
  switch(sel){
    case 0: return g_xp;  case 1: return g_s1;  case 2: return g_s2;
    case 3: return g_qkv2;case 4: return g_up1; case 5: return g_up2;
    case 6: return g_qkv; case 7: return g_xre;
  }
  return g_xp;
}

// ---------------- xp = channel-shifted x ----------------
__global__ void k_xp(const float* __restrict__ x){
  int i = blockIdx.x*256 + threadIdx.x;
  if (i >= BB*CC*N0) return;
  int c = (i / N0) % CC;
  g_xp[i] = (c < CC-1) ? x[i + N0] : x[i];
}

// ---------------- r x r average pool from g_xp ----------------
__global__ void k_pool(int outSel, int r, int Wo, int total){
  int i = blockIdx.x*256 + threadIdx.x;
  if (i >= total) return;
  float* out = buf_ptr(outSel);
  int no = Wo*Wo;
  int p = i % no; int bc = i / no;
  int oy = p / Wo, ox = p % Wo;
  const float* ip = g_xp + (size_t)bc*N0;
  float s = 0.f;
  for (int dy=0; dy<r; dy++)
    for (int dx=0; dx<r; dx++)
      s += ip[(oy*r+dy)*WW + (ox*r+dx)];
  out[i] = s / (float)(r*r);
}

// ---------------- generic tiled GEMM: out[b,o,p] = bias[o] + sum W[o,c]*src[b,c,p]
// tiles: 64 outputs x 64 pixels per block, thread = 4x4 micro-tile
__global__ void __launch_bounds__(256) k_gemm(
    int srcSel0, int srcSel1, int srcSel2, int nchunk, int srcCB, int srcOff,
    const float* __restrict__ w, int useW2, int wstride,
    const float* __restrict__ bias, int outSel, int n, int zero_aux)
{
  __shared__ float sw[64*64];
  __shared__ float sx[64*64];
  int tid = threadIdx.x;
  if (zero_aux && blockIdx.x==0 && blockIdx.y==0 && blockIdx.z==0) {
    for (int i=tid;i<BB*128;i+=256)  g_norms[i]=0.f;
    for (int i=tid;i<BB*1024;i+=256) g_gram[i]=0.f;
  }
  int b = blockIdx.z;
  int M = gridDim.y*64;
  int oBase = blockIdx.y*64;
  int pBase = blockIdx.x*64;
  int tx = tid & 15, ty = tid >> 4;
  float acc[4][4] = {};
  const float* wb = useW2 ? (g_W2 + (size_t)b*4096) : w;
  float* outp = buf_ptr(outSel);

  for (int ch=0; ch<nchunk; ch++){
    const float* src = buf_ptr(ch==0 ? srcSel0 : (ch==1 ? srcSel1 : srcSel2));
    #pragma unroll
    for (int k=0;k<4;k++){          // 4*256 float4 = 4096 floats = 64x64 tile
      int lin = tid + k*256;
      int cc = lin >> 4, pv = lin & 15;
      float4 v = *(const float4*)(src + ((size_t)b*srcCB + srcOff + cc)*n + pBase + pv*4);
      *(float4*)(sx + cc*64 + pv*4) = v;
    }
    #pragma unroll
    for (int k=0;k<16;k++){         // 16*256 scalars = 4096 = 64x64 weights
      int lin = tid + k*256;
      int oo = lin >> 6, cc2 = lin & 63;
      sw[oo*64+cc2] = wb[(size_t)(oBase+oo)*wstride + ch*64 + cc2];
    }
    __syncthreads();
    #pragma unroll 4
    for (int cc=0; cc<64; cc++){
      float4 xv = *(const float4*)(sx + cc*64 + tx*4);
      #pragma unroll
      for (int r=0;r<4;r++){
        float wv = sw[(ty*4+r)*64 + cc];
        acc[r][0] += wv * xv.x;
        acc[r][1] += wv * xv.y;
        acc[r][2] += wv * xv.z;
        acc[r][3] += wv * xv.w;
      }
    }
    __syncthreads();
  }
  #pragma unroll
  for (int r=0;r<4;r++){
    int o = oBase + ty*4 + r;
    float bv = bias[o];
    float4 ov;
    ov.x = acc[r][0]+bv; ov.y = acc[r][1]+bv; ov.z = acc[r][2]+bv; ov.w = acc[r][3]+bv;
    *(float4*)(outp + ((size_t)b*M + o)*n + pBase + tx*4) = ov;
  }
}

// ---------------- dilated(2) 3x3 depthwise conv + per-channel sumsq (q,k only)
__global__ void __launch_bounds__(256) k_dwconv(
    const float* __restrict__ dw, const float* __restrict__ db, int Hs, int Ws)
{
  int n = Hs*Ws;
  int o = blockIdx.y, b = blockIdx.z;
  int p = blockIdx.x*256 + threadIdx.x;
  float sq = 0.f;
  if (p < n){
    int hy = p / Ws, wx = p - hy*Ws;
    const float* ip = g_qkv + ((size_t)b*192 + o)*n;
    const float* wp = dw + o*9;
    float acc = db[o];
    #pragma unroll
    for (int i=0;i<3;i++){
      int hh = hy + 2*i - 2;
      if (hh < 0 || hh >= Hs) continue;
      #pragma unroll
      for (int j=0;j<3;j++){
        int ww = wx + 2*j - 2;
        if (ww < 0 || ww >= Ws) continue;
        acc += ip[hh*Ws+ww]*wp[i*3+j];
      }
    }
    g_qkv2[((size_t)b*192+o)*n + p] = acc;
    if (o < 128) sq = acc*acc;
  }
  __shared__ float red[256];
  red[threadIdx.x] = sq;
  __syncthreads();
  for (int s=128; s>0; s>>=1){
    if (threadIdx.x < s) red[threadIdx.x] += red[threadIdx.x+s];
    __syncthreads();
  }
  if (threadIdx.x==0 && o<128) atomicAdd(&g_norms[b*128+o], red[0]);
}

// ---------------- partial gram G[b,h,c,d] = sum_p q[c,p]*k[d,p] (atomic accumulate)
__global__ void __launch_bounds__(256) k_gram(int n)
{
  int hh = blockIdx.y, b = blockIdx.z;
  int tid = threadIdx.x;
  int c = tid >> 4, d = tid & 15;
  __shared__ float sq[16*65], sk[16*65];
  int p0 = blockIdx.x * 2304;
  int p1 = min(n, p0 + 2304);
  float acc = 0.f;
  for (int t0=p0; t0<p1; t0+=64){
    #pragma unroll
    for (int k=0;k<4;k++){
      int lin = tid + k*256;
      int r = lin >> 6, cc = lin & 63;
      sq[r*65+cc] = g_qkv2[((size_t)b*192 + hh*16 + r)*n + t0 + cc];
      sk[r*65+cc] = g_qkv2[((size_t)b*192 + 64 + hh*16 + r)*n + t0 + cc];
    }
    __syncthreads();
    #pragma unroll 8
    for (int t=0;t<64;t++) acc += sq[c*65+t]*sk[d*65+t];
    __syncthreads();
  }
  atomicAdd(&g_gram[((b*4+hh)*16+c)*16+d], acc);
}

// ---------------- normalize gram, softmax rows, fold proj weights: W2 = pw @ attn
__global__ void k_attn2(const float* __restrict__ temp, const float* __restrict__ pw)
{
  int hh = blockIdx.x, b = blockIdx.y;
  int tid = threadIdx.x;
  int c = tid >> 4, d = tid & 15;
  __shared__ float at[16][16];
  float nq = fmaxf(sqrtf(g_norms[b*128 + hh*16 + c]), 1e-12f);
  float nk = fmaxf(sqrtf(g_norms[b*128 + 64 + hh*16 + d]), 1e-12f);
  at[c][d] = g_gram[((b*4+hh)*16+c)*16+d] / (nq*nk) * temp[hh];
  __syncthreads();
  if (tid < 16){
    float m = -1e30f;
    for (int j=0;j<16;j++) m = fmaxf(m, at[tid][j]);
    float s = 0.f;
    for (int j=0;j<16;j++){ float e = expf(at[tid][j]-m); at[tid][j]=e; s+=e; }
    float inv = 1.f/s;
    for (int j=0;j<16;j++) at[tid][j] *= inv;
  }
  __syncthreads();
  #pragma unroll
  for (int r=0;r<4;r++){
    int lin = tid*4 + r;
    int o = lin >> 4, dd = lin & 15;
    float s = 0.f;
    #pragma unroll
    for (int ci=0;ci<16;ci++) s += pw[o*64 + hh*16 + ci]*at[ci][dd];
    g_W2[b*4096 + o*64 + hh*16 + dd] = s;
  }
}

// ---------------- bilinear upsample (half-pixel, edge clamp == jax.image.resize)
__global__ void k_up(int inSel, int outSel, int hin)
{
  int i = blockIdx.x*256 + threadIdx.x;
  if (i >= BB*CC*N0) return;
  const float* in = buf_ptr(inSel);
  float* out = buf_ptr(outSel);
  int p = i % N0; int bc = i / N0;
  int oy = p / WW, ox = p % WW;
  float r = (float)hin / (float)HH;
  float sy = (oy + 0.5f)*r - 0.5f;
  float sxx = (ox + 0.5f)*r - 0.5f;
  int y0 = (int)floorf(sy), x0 = (int)floorf(sxx);
  float fy = sy - y0, fx = sxx - x0;
  int y0c = min(max(y0,0), hin-1), y1c = min(max(y0+1,0), hin-1);
  int x0c = min(max(x0,0), hin-1), x1c = min(max(x0+1,0), hin-1);
  const float* ip = in + (size_t)bc*hin*hin;
  float v = (1.f-fy)*((1.f-fx)*ip[y0c*hin+x0c] + fx*ip[y0c*hin+x1c])
          +      fy *((1.f-fx)*ip[y1c*hin+x0c] + fx*ip[y1c*hin+x1c]);
  out[i] = v;
}

// ---------------- mamba: one warp per pixel-sequence (lane = d_inner channel)
__global__ void __launch_bounds__(256) k_mamba(
    const float* __restrict__ in_w, const float* __restrict__ conv_w, const float* __restrict__ conv_b,
    const float* __restrict__ xproj_w, const float* __restrict__ dtw_g, const float* __restrict__ dtb_g,
    const float* __restrict__ Alog, const float* __restrict__ Dg, const float* __restrict__ out_w)
{
  __shared__ float s_inw[1024];   // (64,16)
  __shared__ float s_xpw[1056];   // (33,32)
  __shared__ float s_cw[128];     // (32,4)
  __shared__ float s_cb[32], s_dtw[32], s_dtb[32], s_D[32];
  __shared__ float s_A[512];      // -exp(Alog)  (32,16)
  __shared__ float s_outw[512];   // (16,32)
  __shared__ float s_stage[8][128];
  int tid = threadIdx.x;
  for (int i=tid;i<1024;i+=256) s_inw[i]=in_w[i];
  for (int i=tid;i<1056;i+=256) s_xpw[i]=xproj_w[i];
  for (int i=tid;i<128;i+=256)  s_cw[i]=conv_w[i];
  if (tid<32){ s_cb[tid]=conv_b[tid]; s_dtw[tid]=dtw_g[tid]; s_dtb[tid]=dtb_g[tid]; s_D[tid]=Dg[tid]; }
  for (int i=tid;i<512;i+=256){ s_A[i] = -expf(Alog[i]); s_outw[i]=out_w[i]; }
  __syncthreads();

  int warp = tid >> 5, lane = tid & 31;
  int nseq = blockIdx.x*8 + warp;               // 0..36863
  int b = nseq / N0, p = nseq - b*N0;
  const float* src = g_xre + (size_t)b*64*N0 + p;
  float* stg = s_stage[warp];

  stg[lane]      = src[(size_t)lane*N0];
  stg[32 + lane] = src[(size_t)(32+lane)*N0];
  __syncwarp();

  float xi[4], zz[4];
  #pragma unroll
  for (int t=0;t<4;t++){
    float a = 0.f, c2 = 0.f;
    #pragma unroll
    for (int g=0; g<16; g++){
      float xv = stg[t*16+g];
      a  += xv * s_inw[lane*16+g];
      c2 += xv * s_inw[(32+lane)*16+g];
    }
    xi[t]=a; zz[t]=c2;
  }
  // causal depthwise conv over L=4 (pad left 3)
  float u[4];
  #pragma unroll
  for (int t=0;t<4;t++){
    float acc = s_cb[lane];
    #pragma unroll
    for (int k=0;k<4;k++){
      int j = t + k - 3;
      if (j >= 0) acc += xi[j]*s_cw[lane*4+k];
    }
    u[t] = siluf(acc);
  }
  __syncwarp();
  #pragma unroll
  for (int t=0;t<4;t++) stg[t*32+lane] = u[t];
  __syncwarp();
  // xdbl = u @ xproj^T : lane j accumulates row 1+j (B rows 1..16, C rows 17..32), all lanes do dt row 0
  float dtr[4], bc[4];
  #pragma unroll
  for (int t=0;t<4;t++){
    float dr = 0.f, bv = 0.f;
    #pragma unroll
    for (int dd=0; dd<32; dd++){
      float uv = stg[t*32+dd];
      dr += uv * s_xpw[dd];
      bv += uv * s_xpw[(1+lane)*32 + dd];
    }
    dtr[t]=dr; bc[t]=bv;
  }
  float dt[4];
  #pragma unroll
  for (int t=0;t<4;t++){
    float si = dtr[t]*s_dtw[lane] + s_dtb[lane];
    dt[t] = (si > 20.f) ? si : log1pf(expf(si));
  }
  __syncwarp();
  #pragma unroll
  for (int t=0;t<4;t++) stg[t*32+lane] = bc[t];  // lanes 0..15 = B[t,s], 16..31 = C[t,s]
  __syncwarp();

  float hs[16];
  #pragma unroll
  for (int s=0;s<16;s++) hs[s]=0.f;
  float y[4];
  #pragma unroll
  for (int t=0;t<4;t++){
    float du = dt[t]*u[t];
    float yt = 0.f;
    #pragma unroll
    for (int s=0;s<16;s++){
      float dA = expf(dt[t]*s_A[lane*16+s]);
      hs[s] = dA*hs[s] + du*stg[t*32+s];
      yt += hs[s]*stg[t*32+16+s];
    }
    y[t] = (yt + u[t]*s_D[lane]) * siluf(zz[t]);
  }
  __syncwarp();
  #pragma unroll
  for (int t=0;t<4;t++) stg[t*32+lane] = y[t];
  __syncwarp();
  if (lane < 16){
    float* dst = g_xr + (size_t)b*64*N0 + p;
    #pragma unroll
    for (int t=0;t<4;t++){
      float acc = 0.f;
      #pragma unroll
      for (int dd=0; dd<32; dd++) acc += stg[t*32+dd]*s_outw[lane*32+dd];
      dst[(size_t)(t*16+lane)*N0] = acc;
    }
  }
}

// ---------------- groupnorm stats (16 groups total)
__global__ void k_gnstat()
{
  int bg = blockIdx.x;               // b*4 + g
  int b = bg >> 2, g = bg & 3;
  const float* base = g_xr + ((size_t)b*64 + g*16)*N0;
  float s=0.f, s2=0.f;
  for (int i=threadIdx.x; i<16*N0; i+=256){ float v = base[i]; s+=v; s2+=v*v; }
  __shared__ float rs[256], rq[256];
  rs[threadIdx.x]=s; rq[threadIdx.x]=s2;
  __syncthreads();
  for (int k=128;k>0;k>>=1){
    if (threadIdx.x<k){ rs[threadIdx.x]+=rs[threadIdx.x+k]; rq[threadIdx.x]+=rq[threadIdx.x+k]; }
    __syncthreads();
  }
  if (threadIdx.x==0){
    float cnt = 16.f*N0;
    float mean = rs[0]/cnt;
    float var = rq[0]/cnt - mean*mean;
    g_gnstat[bg*2]   = mean;
    g_gnstat[bg*2+1] = rsqrtf(var + 1e-5f);
  }
}

// ---------------- groupnorm apply + silu + residual
__global__ void k_gnout(const float* __restrict__ x, const float* __restrict__ gw,
                        const float* __restrict__ gb, float* __restrict__ out)
{
  int i = blockIdx.x*256 + threadIdx.x;
  if (i >= BB*CC*N0) return;
  int c = (i / N0) % 64;
  int b = i / (64*N0);
  int bg = b*4 + (c>>4);
  float mean = g_gnstat[bg*2], inv = g_gnstat[bg*2+1];
  float v = (g_xr[i]-mean)*inv*gw[c] + gb[c];
  out[i] = siluf(v) + x[i];
}

// ---------------- host ----------------
extern "C" void kernel_launch(void* const* d_in, const int* in_sizes, int n_in,
                              void* d_out, int out_size)
{
  (void)in_sizes; (void)n_in; (void)out_size;
  const float* x        = (const float*)d_in[0];
  const float* qkv_w    = (const float*)d_in[1];
  const float* qkv_b    = (const float*)d_in[2];
  const float* dw_w     = (const float*)d_in[3];
  const float* dw_b     = (const float*)d_in[4];
  const float* po_w     = (const float*)d_in[5];
  const float* po_b     = (const float*)d_in[6];
  const float* temp     = (const float*)d_in[7];
  const float* prca_w   = (const float*)d_in[8];
  const float* prca_b   = (const float*)d_in[9];
  const float* in_w     = (const float*)d_in[10];
  const float* conv_w   = (const float*)d_in[11];
  const float* conv_b   = (const float*)d_in[12];
  const float* xproj_w  = (const float*)d_in[13];
  const float* dtproj_w = (const float*)d_in[14];
  const float* dtproj_b = (const float*)d_in[15];
  const float* Alog     = (const float*)d_in[16];
  const float* Dp       = (const float*)d_in[17];
  const float* out_w    = (const float*)d_in[18];
  const float* gn_w     = (const float*)d_in[19];
  const float* gn_b     = (const float*)d_in[20];
  float* out = (float*)d_out;

  k_xp<<<(BB*CC*N0+255)/256, 256>>>(x);
  k_pool<<<(BB*CC*N1+255)/256, 256>>>(1, 2, 48, BB*CC*N1);
  k_pool<<<(BB*CC*N2+255)/256, 256>>>(2, 4, 24, BB*CC*N2);

  const int scSel[3] = {0, 1, 2};
  const int scH[3]   = {96, 48, 24};
  for (int s=0; s<3; s++){
    int hs = scH[s];
    int n = hs*hs;
    for (int j=0; j<3; j++){
      int i = 3*s + j;
      // qkv GEMM (zeroes norm/gram accumulators for this block)
      k_gemm<<<dim3(n/64, 3, BB), 256>>>(scSel[s],0,0, 1, 64, 0,
                                         qkv_w + (size_t)i*192*64, 0, 64,
                                         qkv_b + i*192, 6 /*g_qkv*/, n, 1);
      // depthwise dilated conv + sumsq accumulation
      k_dwconv<<<dim3((n+255)/256, 192, BB), 256>>>(dw_w + (size_t)i*192*9, dw_b + i*192, hs, hs);
      // gram partials
      k_gram<<<dim3((n+2303)/2304, 4, BB), 256>>>(n);
      // normalize + softmax + fold proj weights
      k_attn2<<<dim3(4, BB), 256>>>(temp + i*4, po_w + (size_t)i*64*64);
      // epilogue GEMM over v with per-batch W2, writes back into scale buffer
      k_gemm<<<dim3(n/64, 1, BB), 256>>>(3,0,0, 1, 192, 128,
                                         nullptr, 1, 64,
                                         po_b + i*64, scSel[s], n, 0);
    }
  }

  k_up<<<(BB*CC*N0+255)/256, 256>>>(1, 4, 48);
  k_up<<<(BB*CC*N0+255)/256, 256>>>(2, 5, 24);

  // prca: concat(s0, up(s1), up(s2)) -> 64ch via (64,192) weight, 3 K-chunks
  k_gemm<<<dim3(N0/64, 1, BB), 256>>>(0, 4, 5, 3, 64, 0,
                                      prca_w, 0, 192,
                                      prca_b, 7 /*g_xre*/, N0, 0);

  k_mamba<<<4608, 256>>>(in_w, conv_w, conv_b, xproj_w, dtproj_w, dtproj_b, Alog, Dp, out_w);

  k_gnstat<<<16, 256>>>();
  k_gnout<<<(BB*CC*N0+255)/256, 256>>>(x, gn_w, gn_b, out);
}

// round 3
// speedup vs baseline: 1.1272x; 1.1272x over previous
#include <cuda_runtime.h>
#include <math.h>

#define BB 4
#define CC 64
#define HH 96
#define WW 96
#define N0 (HH*WW)      // 9216
#define N1 (48*48)      // 2304
#define N2 (24*24)      // 576

typedef unsigned long long u64t;

// ------------- scratch (static device globals; no allocation) -------------
__device__ __align__(16) float g_xp [BB*CC*N0];
__device__ __align__(16) float g_s1 [BB*CC*N1];
__device__ __align__(16) float g_s2 [BB*CC*N2];
__device__ __align__(16) float g_qkv [BB*192*N0];
__device__ __align__(16) float g_qkv2[BB*192*N0];
__device__ __align__(16) float g_y1[BB*CC*N1];
__device__ __align__(16) float g_y2[BB*CC*N2];
__device__ __align__(16) float g_xre[BB*CC*N0];
__device__ __align__(16) float g_xr [BB*CC*N0];
__device__ __align__(16) float g_norms[BB*128];
__device__ __align__(16) float g_gram[BB*4*16*16];
__device__ __align__(16) float g_W2[BB*64*64];
__device__ __align__(16) float g_gnstat[BB*4*2];

__device__ __forceinline__ float siluf(float x){ return x / (1.f + __expf(-x)); }

__device__ __forceinline__ float* buf_ptr(int sel){
  switch(sel){
    case 0: return g_xp;  case 1: return g_s1;  case 2: return g_s2;
    case 3: return g_qkv2;case 4: return g_y1;  case 5: return g_y2;
    case 6: return g_qkv; case 7: return g_xre;
  }
  return g_xp;
}

// ---- packed f32x2 helpers (FFMA2: PTX-only on sm_103a) ----
__device__ __forceinline__ void ffma2(u64t &d, u64t a, u64t b){
  asm("fma.rn.f32x2 %0, %1, %2, %0;" : "+l"(d) : "l"(a), "l"(b));
}
__device__ __forceinline__ u64t dup2(float w){
  u64t r; asm("mov.b64 %0, {%1, %1};" : "=l"(r) : "f"(w)); return r;
}
__device__ __forceinline__ float2 unpack2(u64t v){
  float2 f; asm("mov.b64 {%0, %1}, %2;" : "=f"(f.x), "=f"(f.y) : "l"(v)); return f;
}

// ---------------- xp = channel-shifted x ----------------
__global__ void k_xp(const float* __restrict__ x){
  int i = blockIdx.x*256 + threadIdx.x;
  if (i >= BB*CC*N0) return;
  int c = (i / N0) % CC;
  g_xp[i] = (c < CC-1) ? x[i + N0] : x[i];
}

// ---------------- r x r average pool from g_xp ----------------
__global__ void k_pool(int outSel, int r, int Wo, int total){
  int i = blockIdx.x*256 + threadIdx.x;
  if (i >= total) return;
  float* out = buf_ptr(outSel);
  int no = Wo*Wo;
  int p = i % no; int bc = i / no;
  int oy = p / Wo, ox = p % Wo;
  const float* ip = g_xp + (size_t)bc*N0;
  float s = 0.f;
  for (int dy=0; dy<r; dy++)
    for (int dx=0; dx<r; dx++)
      s += ip[(oy*r+dy)*WW + (ox*r+dx)];
  out[i] = s / (float)(r*r);
}

// ---------------- GEMM: out[b,o,p] = bias[o] + sum_c W[o,c]*src[b,c,p], K=64
// tile: 64 out x NPX px, 256 threads, thread = 4 out x (NPX/16) px, FFMA2 packed
template<int NPX>
__global__ void __launch_bounds__(256) k_gemm(
    int srcSel, int srcCB, int srcOff,
    const float* __restrict__ w, int useW2, int wstride,
    const float* __restrict__ bias, int outSel, int n, int zero_aux)
{
  constexpr int PXT = NPX/16;     // px per thread
  constexpr int PP  = PXT/2;      // f32x2 pairs per thread
  __shared__ float sx[64*NPX];
  __shared__ float swt[64*68];    // transposed weights, padded
  int tid = threadIdx.x;
  if (zero_aux && blockIdx.x==0 && blockIdx.y==0 && blockIdx.z==0){
    for (int i=tid;i<BB*128;i+=256)  g_norms[i]=0.f;
    for (int i=tid;i<BB*1024;i+=256) g_gram[i]=0.f;
  }
  int b = blockIdx.z;
  int M = gridDim.y*64;
  int oBase = blockIdx.y*64, pBase = blockIdx.x*NPX;
  int tx = tid & 15, ty = tid >> 4;
  const float* src = buf_ptr(srcSel) + ((size_t)b*srcCB + srcOff)*n + pBase;
  const float* wb = useW2 ? (g_W2 + (size_t)b*4096) : w;

  #pragma unroll
  for (int k=0;k<PXT;k++){
    int lin = k*256 + tid;
    int px4 = lin & (NPX/4 - 1);
    int cc  = lin / (NPX/4);
    *(float4*)(sx + cc*NPX + px4*4) = *(const float4*)(src + (size_t)cc*n + px4*4);
  }
  #pragma unroll
  for (int k=0;k<16;k++){
    int lin = k*256 + tid;
    int cc = lin & 63, oo = lin >> 6;
    swt[cc*68 + oo] = wb[(size_t)(oBase+oo)*wstride + cc];
  }
  __syncthreads();

  u64t acc[4][PP];
  #pragma unroll
  for (int r=0;r<4;r++)
    #pragma unroll
    for (int j=0;j<PP;j++) acc[r][j]=0ull;

  #pragma unroll 4
  for (int cc=0; cc<64; cc++){
    u64t xp[PP];
    #pragma unroll
    for (int j=0;j<PP;j++) xp[j] = *(const u64t*)(sx + cc*NPX + tx*2 + 32*j);
    float4 w4 = *(const float4*)(swt + cc*68 + ty*4);
    u64t w0=dup2(w4.x), w1=dup2(w4.y), w2=dup2(w4.z), w3=dup2(w4.w);
    #pragma unroll
    for (int j=0;j<PP;j++){
      ffma2(acc[0][j], w0, xp[j]);
      ffma2(acc[1][j], w1, xp[j]);
      ffma2(acc[2][j], w2, xp[j]);
      ffma2(acc[3][j], w3, xp[j]);
    }
  }
  float* outp = buf_ptr(outSel) + (size_t)b*M*n + pBase;
  #pragma unroll
  for (int r=0;r<4;r++){
    int o = oBase + ty*4 + r;
    float bv = bias ? bias[o] : 0.f;
    #pragma unroll
    for (int j=0;j<PP;j++){
      float2 v = unpack2(acc[r][j]);
      v.x += bv; v.y += bv;
      *(float2*)(outp + (size_t)o*n + tx*2 + 32*j) = v;
    }
  }
}

// ---------------- dilated(2) 3x3 depthwise conv + per-channel sumsq (q,k only)
__global__ void __launch_bounds__(256) k_dwconv(
    const float* __restrict__ dw, const float* __restrict__ db, int Hs, int Ws)
{
  int n = Hs*Ws;
  int o = blockIdx.y, b = blockIdx.z;
  int p = blockIdx.x*256 + threadIdx.x;
  float sq = 0.f;
  if (p < n){
    int hy = p / Ws, wx = p - hy*Ws;
    const float* ip = g_qkv + ((size_t)b*192 + o)*n;
    const float* wp = dw + o*9;
    float acc = db[o];
    #pragma unroll
    for (int i=0;i<3;i++){
      int hh = hy + 2*i - 2;
      if (hh < 0 || hh >= Hs) continue;
      #pragma unroll
      for (int j=0;j<3;j++){
        int ww = wx + 2*j - 2;
        if (ww < 0 || ww >= Ws) continue;
        acc += ip[hh*Ws+ww]*wp[i*3+j];
      }
    }
    g_qkv2[((size_t)b*192+o)*n + p] = acc;
    if (o < 128) sq = acc*acc;
  }
  __shared__ float red[256];
  red[threadIdx.x] = sq;
  __syncthreads();
  for (int s=128; s>0; s>>=1){
    if (threadIdx.x < s) red[threadIdx.x] += red[threadIdx.x+s];
    __syncthreads();
  }
  if (threadIdx.x==0 && o<128) atomicAdd(&g_norms[b*128+o], red[0]);
}

// ---------------- partial gram G[b,h,c,d] = sum_p q[c,p]*k[d,p] (atomic accumulate)
__global__ void __launch_bounds__(256) k_gram(int n)
{
  int hh = blockIdx.y, b = blockIdx.z;
  int tid = threadIdx.x;
  int c = tid >> 4, d = tid & 15;
  __shared__ float sq[16*65], sk[16*65];
  int p0 = blockIdx.x * 2304;
  int p1 = min(n, p0 + 2304);
  float acc = 0.f;
  for (int t0=p0; t0<p1; t0+=64){
    #pragma unroll
    for (int k=0;k<4;k++){
      int lin = tid + k*256;
      int r = lin >> 6, cc = lin & 63;
      sq[r*65+cc] = g_qkv2[((size_t)b*192 + hh*16 + r)*n + t0 + cc];
      sk[r*65+cc] = g_qkv2[((size_t)b*192 + 64 + hh*16 + r)*n + t0 + cc];
    }
    __syncthreads();
    #pragma unroll 8
    for (int t=0;t<64;t++) acc += sq[c*65+t]*sk[d*65+t];
    __syncthreads();
  }
  atomicAdd(&g_gram[((b*4+hh)*16+c)*16+d], acc);
}

// ---------------- normalize gram, softmax rows, fold proj weights: W2 = pw @ attn
__global__ void k_attn2(const float* __restrict__ temp, const float* __restrict__ pw)
{
  int hh = blockIdx.x, b = blockIdx.y;
  int tid = threadIdx.x;
  int c = tid >> 4, d = tid & 15;
  __shared__ float at[16][16];
  float nq = fmaxf(sqrtf(g_norms[b*128 + hh*16 + c]), 1e-12f);
  float nk = fmaxf(sqrtf(g_norms[b*128 + 64 + hh*16 + d]), 1e-12f);
  at[c][d] = g_gram[((b*4+hh)*16+c)*16+d] / (nq*nk) * temp[hh];
  __syncthreads();
  if (tid < 16){
    float m = -1e30f;
    for (int j=0;j<16;j++) m = fmaxf(m, at[tid][j]);
    float s = 0.f;
    for (int j=0;j<16;j++){ float e = __expf(at[tid][j]-m); at[tid][j]=e; s+=e; }
    float inv = 1.f/s;
    for (int j=0;j<16;j++) at[tid][j] *= inv;
  }
  __syncthreads();
  #pragma unroll
  for (int r=0;r<4;r++){
    int lin = tid*4 + r;
    int o = lin >> 4, dd = lin & 15;
    float s = 0.f;
    #pragma unroll
    for (int ci=0;ci<16;ci++) s += pw[o*64 + hh*16 + ci]*at[ci][dd];
    g_W2[b*4096 + o*64 + hh*16 + dd] = s;
  }
}

// ---------------- bilinear sample (half-pixel, edge clamp == jax.image.resize)
__device__ __forceinline__ float bil(const float* __restrict__ ip, int hin, int oy, int ox){
  float r = (float)hin / (float)HH;
  float sy = (oy + 0.5f)*r - 0.5f;
  float sxx = (ox + 0.5f)*r - 0.5f;
  int y0 = (int)floorf(sy), x0 = (int)floorf(sxx);
  float fy = sy - y0, fx = sxx - x0;
  int y0c = min(max(y0,0), hin-1), y1c = min(max(y0+1,0), hin-1);
  int x0c = min(max(x0,0), hin-1), x1c = min(max(x0+1,0), hin-1);
  return (1.f-fy)*((1.f-fx)*ip[y0c*hin+x0c] + fx*ip[y0c*hin+x1c])
       +      fy *((1.f-fx)*ip[y1c*hin+x0c] + fx*ip[y1c*hin+x1c]);
}

// ---------------- xre += up(y1) + up(y2)  (upsample folded through linear prca)
__global__ void k_upadd(){
  int i = blockIdx.x*256 + threadIdx.x;
  if (i >= BB*CC*N0) return;
  int p = i % N0; int bc = i / N0;
  int oy = p / WW, ox = p % WW;
  float v = bil(g_y1 + (size_t)bc*N1, 48, oy, ox)
          + bil(g_y2 + (size_t)bc*N2, 24, oy, ox);
  g_xre[i] += v;
}

// ---------------- mamba: one warp per pixel-sequence (lane = d_inner channel)
__global__ void __launch_bounds__(256) k_mamba(
    const float* __restrict__ in_w, const float* __restrict__ conv_w, const float* __restrict__ conv_b,
    const float* __restrict__ xproj_w, const float* __restrict__ dtw_g, const float* __restrict__ dtb_g,
    const float* __restrict__ Alog, const float* __restrict__ Dg, const float* __restrict__ out_w)
{
  __shared__ float s_inw[1024];   // (64,16)
  __shared__ float s_xpw[1056];   // (33,32)
  __shared__ float s_cw[128];     // (32,4)
  __shared__ float s_cb[32], s_dtw[32], s_dtb[32], s_D[32];
  __shared__ float s_A[512];      // -exp(Alog)  (32,16)
  __shared__ float s_outw[512];   // (16,32)
  __shared__ float s_stage[8][128];
  int tid = threadIdx.x;
  for (int i=tid;i<1024;i+=256) s_inw[i]=in_w[i];
  for (int i=tid;i<1056;i+=256) s_xpw[i]=xproj_w[i];
  for (int i=tid;i<128;i+=256)  s_cw[i]=conv_w[i];
  if (tid<32){ s_cb[tid]=conv_b[tid]; s_dtw[tid]=dtw_g[tid]; s_dtb[tid]=dtb_g[tid]; s_D[tid]=Dg[tid]; }
  for (int i=tid;i<512;i+=256){ s_A[i] = -expf(Alog[i]); s_outw[i]=out_w[i]; }
  __syncthreads();

  int warp = tid >> 5, lane = tid & 31;
  int nseq = blockIdx.x*8 + warp;               // 0..36863
  int b = nseq / N0, p = nseq - b*N0;
  const float* src = g_xre + (size_t)b*64*N0 + p;
  float* stg = s_stage[warp];

  stg[lane]      = src[(size_t)lane*N0];
  stg[32 + lane] = src[(size_t)(32+lane)*N0];
  __syncwarp();

  float xi[4], zz[4];
  #pragma unroll
  for (int t=0;t<4;t++){
    float a = 0.f, c2 = 0.f;
    #pragma unroll
    for (int g=0; g<16; g++){
      float xv = stg[t*16+g];
      a  += xv * s_inw[lane*16+g];
      c2 += xv * s_inw[(32+lane)*16+g];
    }
    xi[t]=a; zz[t]=c2;
  }
  // causal depthwise conv over L=4 (pad left 3)
  float u[4];
  #pragma unroll
  for (int t=0;t<4;t++){
    float acc = s_cb[lane];
    #pragma unroll
    for (int k=0;k<4;k++){
      int j = t + k - 3;
      if (j >= 0) acc += xi[j]*s_cw[lane*4+k];
    }
    u[t] = siluf(acc);
  }
  __syncwarp();
  #pragma unroll
  for (int t=0;t<4;t++) stg[t*32+lane] = u[t];
  __syncwarp();
  // xdbl = u @ xproj^T : lane j accumulates row 1+j (B rows 1..16, C rows 17..32)
  float dtr[4], bc[4];
  #pragma unroll
  for (int t=0;t<4;t++){
    float dr = 0.f, bv = 0.f;
    #pragma unroll
    for (int dd=0; dd<32; dd++){
      float uv = stg[t*32+dd];
      dr += uv * s_xpw[dd];
      bv += uv * s_xpw[(1+lane)*32 + dd];
    }
    dtr[t]=dr; bc[t]=bv;
  }
  float dt[4];
  #pragma unroll
  for (int t=0;t<4;t++){
    float si = dtr[t]*s_dtw[lane] + s_dtb[lane];
    dt[t] = (si > 20.f) ? si : __logf(1.f + __expf(si));
  }
  __syncwarp();
  #pragma unroll
  for (int t=0;t<4;t++) stg[t*32+lane] = bc[t];  // lanes 0..15 = B[t,s], 16..31 = C[t,s]
  __syncwarp();

  float hs[16];
  #pragma unroll
  for (int s=0;s<16;s++) hs[s]=0.f;
  float y[4];
  #pragma unroll
  for (int t=0;t<4;t++){
    float du = dt[t]*u[t];
    float yt = 0.f;
    #pragma unroll
    for (int s=0;s<16;s++){
      float dA = __expf(dt[t]*s_A[lane*16+s]);
      hs[s] = dA*hs[s] + du*stg[t*32+s];
      yt += hs[s]*stg[t*32+16+s];
    }
    y[t] = (yt + u[t]*s_D[lane]) * siluf(zz[t]);
  }
  __syncwarp();
  #pragma unroll
  for (int t=0;t<4;t++) stg[t*32+lane] = y[t];
  __syncwarp();
  if (lane < 16){
    float* dst = g_xr + (size_t)b*64*N0 + p;
    #pragma unroll
    for (int t=0;t<4;t++){
      float acc = 0.f;
      #pragma unroll
      for (int dd=0; dd<32; dd++) acc += stg[t*32+dd]*s_outw[lane*32+dd];
      dst[(size_t)(t*16+lane)*N0] = acc;
    }
  }
}

// ---------------- groupnorm stats (16 groups total)
__global__ void k_gnstat()
{
  int bg = blockIdx.x;               // b*4 + g
  int b = bg >> 2, g = bg & 3;
  const float* base = g_xr + ((size_t)b*64 + g*16)*N0;
  float s=0.f, s2=0.f;
  for (int i=threadIdx.x; i<16*N0; i+=256){ float v = base[i]; s+=v; s2+=v*v; }
  __shared__ float rs[256], rq[256];
  rs[threadIdx.x]=s; rq[threadIdx.x]=s2;
  __syncthreads();
  for (int k=128;k>0;k>>=1){
    if (threadIdx.x<k){ rs[threadIdx.x]+=rs[threadIdx.x+k]; rq[threadIdx.x]+=rq[threadIdx.x+k]; }
    __syncthreads();
  }
  if (threadIdx.x==0){
    float cnt = 16.f*N0;
    float mean = rs[0]/cnt;
    float var = rq[0]/cnt - mean*mean;
    g_gnstat[bg*2]   = mean;
    g_gnstat[bg*2+1] = rsqrtf(var + 1e-5f);
  }
}

// ---------------- groupnorm apply + silu + residual
__global__ void k_gnout(const float* __restrict__ x, const float* __restrict__ gw,
                        const float* __restrict__ gb, float* __restrict__ out)
{
  int i = blockIdx.x*256 + threadIdx.x;
  if (i >= BB*CC*N0) return;
  int c = (i / N0) % 64;
  int b = i / (64*N0);
  int bg = b*4 + (c>>4);
  float mean = g_gnstat[bg*2], inv = g_gnstat[bg*2+1];
  float v = (g_xr[i]-mean)*inv*gw[c] + gb[c];
  out[i] = siluf(v) + x[i];
}

// ---------------- host ----------------
extern "C" void kernel_launch(void* const* d_in, const int* in_sizes, int n_in,
                              void* d_out, int out_size)
{
  (void)in_sizes; (void)n_in; (void)out_size;
  const float* x        = (const float*)d_in[0];
  const float* qkv_w    = (const float*)d_in[1];
  const float* qkv_b    = (const float*)d_in[2];
  const float* dw_w     = (const float*)d_in[3];
  const float* dw_b     = (const float*)d_in[4];
  const float* po_w     = (const float*)d_in[5];
  const float* po_b     = (const float*)d_in[6];
  const float* temp     = (const float*)d_in[7];
  const float* prca_w   = (const float*)d_in[8];
  const float* prca_b   = (const float*)d_in[9];
  const float* in_w     = (const float*)d_in[10];
  const float* conv_w   = (const float*)d_in[11];
  const float* conv_b   = (const float*)d_in[12];
  const float* xproj_w  = (const float*)d_in[13];
  const float* dtproj_w = (const float*)d_in[14];
  const float* dtproj_b = (const float*)d_in[15];
  const float* Alog     = (const float*)d_in[16];
  const float* Dp       = (const float*)d_in[17];
  const float* out_w    = (const float*)d_in[18];
  const float* gn_w     = (const float*)d_in[19];
  const float* gn_b     = (const float*)d_in[20];
  float* out = (float*)d_out;

  k_xp<<<(BB*CC*N0+255)/256, 256>>>(x);
  k_pool<<<(BB*CC*N1+255)/256, 256>>>(1, 2, 48, BB*CC*N1);
  k_pool<<<(BB*CC*N2+255)/256, 256>>>(2, 4, 24, BB*CC*N2);

  const int scSel[3] = {0, 1, 2};
  const int scH[3]   = {96, 48, 24};
  for (int s=0; s<3; s++){
    int hs = scH[s];
    int n = hs*hs;
    for (int j=0; j<3; j++){
      int i = 3*s + j;
      // qkv GEMM (also zeroes norm/gram accumulators for this block)
      if (s < 2)
        k_gemm<128><<<dim3(n/128, 3, BB), 256>>>(scSel[s], 64, 0,
            qkv_w + (size_t)i*192*64, 0, 64, qkv_b + i*192, 6, n, 1);
      else
        k_gemm<64><<<dim3(n/64, 3, BB), 256>>>(scSel[s], 64, 0,
            qkv_w + (size_t)i*192*64, 0, 64, qkv_b + i*192, 6, n, 1);
      // depthwise dilated conv + sumsq accumulation
      k_dwconv<<<dim3((n+255)/256, 192, BB), 256>>>(dw_w + (size_t)i*192*9, dw_b + i*192, hs, hs);
      // gram partials
      k_gram<<<dim3((n+2303)/2304, 4, BB), 256>>>(n);
      // normalize + softmax + fold proj weights
      k_attn2<<<dim3(4, BB), 256>>>(temp + i*4, po_w + (size_t)i*64*64);
      // epilogue GEMM over v with per-batch W2, writes back into scale buffer
      if (s < 2)
        k_gemm<128><<<dim3(n/128, 1, BB), 256>>>(3, 192, 128,
            nullptr, 1, 64, po_b + i*64, scSel[s], n, 0);
      else
        k_gemm<64><<<dim3(n/64, 1, BB), 256>>>(3, 192, 128,
            nullptr, 1, 64, po_b + i*64, scSel[s], n, 0);
    }
  }

  // prca with upsample folded through the linear map:
  //   xre = W0@s0 + b  (full res), then += up(W1@s1) + up(W2@s2)
  k_gemm<128><<<dim3(N0/128, 1, BB), 256>>>(0, 64, 0, prca_w,       0, 192, prca_b, 7, N0, 0);
  k_gemm<128><<<dim3(N1/128, 1, BB), 256>>>(1, 64, 0, prca_w + 64,  0, 192, nullptr, 4, N1, 0);
  k_gemm<64> <<<dim3(N2/64,  1, BB), 256>>>(2, 64, 0, prca_w + 128, 0, 192, nullptr, 5, N2, 0);
  k_upadd<<<(BB*CC*N0+255)/256, 256>>>();

  k_mamba<<<4608, 256>>>(in_w, conv_w, conv_b, xproj_w, dtproj_w, dtproj_b, Alog, Dp, out_w);

  k_gnstat<<<16, 256>>>();
  k_gnout<<<(BB*CC*N0+255)/256, 256>>>(x, gn_w, gn_b, out);
}

// round 4
// speedup vs baseline: 1.9084x; 1.6930x over previous
#include <cuda_runtime.h>
#include <math.h>

#define BB 4
#define CC 64
#define HH 96
#define WW 96
#define N0 (HH*WW)      // 9216
#define N1 (48*48)      // 2304
#define N2 (24*24)      // 576

typedef unsigned long long u64t;
typedef long long s64t;

// qkv region sizes per scale
#define Q0 ((s64t)BB*192*N0)
#define Q1 ((s64t)BB*192*N1)
#define Q2 ((s64t)BB*192*N2)

// ------------- scratch (static device globals; no allocation) -------------
__device__ __align__(16) float g_xp [BB*CC*N0];
__device__ __align__(16) float g_s1 [BB*CC*N1];
__device__ __align__(16) float g_s2 [BB*CC*N2];
__device__ __align__(16) float g_qkv [Q0+Q1+Q2];
__device__ __align__(16) float g_qkv2[Q0+Q1+Q2];
__device__ __align__(16) float g_y1[BB*CC*N1];
__device__ __align__(16) float g_y2[BB*CC*N2];
__device__ __align__(16) float g_xre[BB*CC*N0];
__device__ __align__(16) float g_xr [BB*CC*N0];
__device__ __align__(16) float g_norms[3*BB*128];
__device__ __align__(16) float g_gram[3*BB*1024];
__device__ __align__(16) float g_W2[3*BB*4096];
__device__ __align__(16) unsigned int g_cnt[3*BB*4];
__device__ __align__(16) float g_gnsum[BB*4];
__device__ __align__(16) float g_gnsq[BB*4];

__device__ __forceinline__ float siluf(float x){ return x / (1.f + __expf(-x)); }

__device__ __forceinline__ float* buf_ptr(int sel){
  switch(sel){
    case 0: return g_xp;  case 1: return g_s1;  case 2: return g_s2;
    case 3: return g_qkv2;case 4: return g_y1;  case 5: return g_y2;
    case 6: return g_qkv; case 7: return g_xre;
  }
  return g_xp;
}

// ---- packed f32x2 helpers (FFMA2: PTX-only on sm_103a) ----
__device__ __forceinline__ void ffma2(u64t &d, u64t a, u64t b){
  asm("fma.rn.f32x2 %0, %1, %2, %0;" : "+l"(d) : "l"(a), "l"(b));
}
__device__ __forceinline__ u64t dup2(float w){
  u64t r; asm("mov.b64 %0, {%1, %1};" : "=l"(r) : "f"(w)); return r;
}
__device__ __forceinline__ float2 unpack2(u64t v){
  float2 f; asm("mov.b64 {%0, %1}, %2;" : "=f"(f.x), "=f"(f.y) : "l"(v)); return f;
}

// ---------------- xp = channel-shifted x ----------------
__global__ void k_xp(const float* __restrict__ x){
  int i = blockIdx.x*256 + threadIdx.x;
  if (i >= BB*CC*N0) return;
  int c = (i / N0) % CC;
  g_xp[i] = (c < CC-1) ? x[i + N0] : x[i];
}

// ---------------- r x r average pool from g_xp ----------------
__global__ void k_pool(int outSel, int r, int Wo, int total){
  int i = blockIdx.x*256 + threadIdx.x;
  if (i >= total) return;
  float* out = buf_ptr(outSel);
  int no = Wo*Wo;
  int p = i % no; int bc = i / no;
  int oy = p / Wo, ox = p % Wo;
  const float* ip = g_xp + (size_t)bc*N0;
  float s = 0.f;
  for (int dy=0; dy<r; dy++)
    for (int dx=0; dx<r; dx++)
      s += ip[(oy*r+dy)*WW + (ox*r+dx)];
  out[i] = s / (float)(r*r);
}

// ---------------- GEMM: out[b,o,p] = bias[o] + sum_c W[o,c]*src[b,c,p], K=64
template<int NPX>
__global__ void __launch_bounds__(256) k_gemm(
    int srcSel, s64t srcBase, int srcCB, int srcOff,
    const float* __restrict__ w, int useW2sc, int wstride,
    const float* __restrict__ bias, int outSel, s64t outBase, int n, int zeroSc)
{
  constexpr int PXT = NPX/16;     // px per thread
  constexpr int PP  = PXT/2;      // f32x2 pairs per thread
  __shared__ float sx[64*NPX];
  __shared__ float swt[64*68];    // transposed weights, padded
  int tid = threadIdx.x;
  if (zeroSc >= 0 && blockIdx.x==0 && blockIdx.y==0 && blockIdx.z==0){
    for (int i=tid;i<BB*128;i+=256)  g_norms[zeroSc*BB*128+i]=0.f;
    for (int i=tid;i<BB*1024;i+=256) g_gram[zeroSc*BB*1024+i]=0.f;
    if (tid < BB*4) g_cnt[zeroSc*BB*4+tid]=0u;
  }
  int b = blockIdx.z;
  int M = gridDim.y*64;
  int oBase = blockIdx.y*64, pBase = blockIdx.x*NPX;
  int tx = tid & 15, ty = tid >> 4;
  const float* src = buf_ptr(srcSel) + srcBase + ((size_t)b*srcCB + srcOff)*n + pBase;
  const float* wb = (useW2sc >= 0) ? (g_W2 + (size_t)useW2sc*BB*4096 + (size_t)b*4096) : w;

  #pragma unroll
  for (int k=0;k<PXT;k++){
    int lin = k*256 + tid;
    int px4 = lin & (NPX/4 - 1);
    int cc  = lin / (NPX/4);
    *(float4*)(sx + cc*NPX + px4*4) = *(const float4*)(src + (size_t)cc*n + px4*4);
  }
  #pragma unroll
  for (int k=0;k<16;k++){
    int lin = k*256 + tid;
    int cc = lin & 63, oo = lin >> 6;
    swt[cc*68 + oo] = wb[(size_t)(oBase+oo)*wstride + cc];
  }
  __syncthreads();

  u64t acc[4][PP];
  #pragma unroll
  for (int r=0;r<4;r++)
    #pragma unroll
    for (int j=0;j<PP;j++) acc[r][j]=0ull;

  #pragma unroll 4
  for (int cc=0; cc<64; cc++){
    u64t xp[PP];
    #pragma unroll
    for (int j=0;j<PP;j++) xp[j] = *(const u64t*)(sx + cc*NPX + tx*2 + 32*j);
    float4 w4 = *(const float4*)(swt + cc*68 + ty*4);
    u64t w0=dup2(w4.x), w1=dup2(w4.y), w2=dup2(w4.z), w3=dup2(w4.w);
    #pragma unroll
    for (int j=0;j<PP;j++){
      ffma2(acc[0][j], w0, xp[j]);
      ffma2(acc[1][j], w1, xp[j]);
      ffma2(acc[2][j], w2, xp[j]);
      ffma2(acc[3][j], w3, xp[j]);
    }
  }
  float* outp = buf_ptr(outSel) + outBase + (size_t)b*M*n + pBase;
  #pragma unroll
  for (int r=0;r<4;r++){
    int o = oBase + ty*4 + r;
    float bv = bias ? bias[o] : 0.f;
    #pragma unroll
    for (int j=0;j<PP;j++){
      float2 v = unpack2(acc[r][j]);
      v.x += bv; v.y += bv;
      *(float2*)(outp + (size_t)o*n + tx*2 + 32*j) = v;
    }
  }
}

// ---------------- dilated(2) 3x3 depthwise conv + per-channel sumsq (q,k only)
__global__ void __launch_bounds__(256) k_dwconv(
    const float* __restrict__ dw, const float* __restrict__ db, int Hs, int Ws,
    s64t qoff, int sc)
{
  int n = Hs*Ws;
  int o = blockIdx.y, b = blockIdx.z;
  int p = blockIdx.x*256 + threadIdx.x;
  float sq = 0.f;
  if (p < n){
    int hy = p / Ws, wx = p - hy*Ws;
    const float* ip = g_qkv + qoff + ((size_t)b*192 + o)*n;
    const float* wp = dw + o*9;
    float acc = db[o];
    #pragma unroll
    for (int i=0;i<3;i++){
      int hh = hy + 2*i - 2;
      if (hh < 0 || hh >= Hs) continue;
      #pragma unroll
      for (int j=0;j<3;j++){
        int ww = wx + 2*j - 2;
        if (ww < 0 || ww >= Ws) continue;
        acc += ip[hh*Ws+ww]*wp[i*3+j];
      }
    }
    g_qkv2[qoff + ((size_t)b*192+o)*n + p] = acc;
    if (o < 128) sq = acc*acc;
  }
  if (o < 128){
    #pragma unroll
    for (int off=16; off; off>>=1) sq += __shfl_down_sync(0xffffffffu, sq, off);
    __shared__ float wsum[8];
    int lane = threadIdx.x & 31, warp = threadIdx.x >> 5;
    if (lane==0) wsum[warp] = sq;
    __syncthreads();
    if (threadIdx.x==0){
      float s = 0.f;
      #pragma unroll
      for (int i=0;i<8;i++) s += wsum[i];
      atomicAdd(&g_norms[sc*BB*128 + b*128 + o], s);
    }
  }
}

// ---------------- gram partials + (last block) softmax + W2 fold
__global__ void __launch_bounds__(256) k_gram(
    int n, s64t qoff, int sc,
    const float* __restrict__ temp, const float* __restrict__ pw)
{
  int hh = blockIdx.y, b = blockIdx.z;
  int tid = threadIdx.x;
  int c = tid >> 4, d = tid & 15;
  __shared__ float sq[16*65], sk[16*65];
  int p0 = blockIdx.x * 2304;
  int p1 = min(n, p0 + 2304);
  float acc = 0.f;
  const float* qbase = g_qkv2 + qoff;
  for (int t0=p0; t0<p1; t0+=64){
    #pragma unroll
    for (int k=0;k<4;k++){
      int lin = tid + k*256;
      int r = lin >> 6, cc = lin & 63;
      sq[r*65+cc] = qbase[((size_t)b*192 + hh*16 + r)*n + t0 + cc];
      sk[r*65+cc] = qbase[((size_t)b*192 + 64 + hh*16 + r)*n + t0 + cc];
    }
    __syncthreads();
    #pragma unroll 8
    for (int t=0;t<64;t++) acc += sq[c*65+t]*sk[d*65+t];
    __syncthreads();
  }
  float* gram = g_gram + (size_t)sc*BB*1024 + ((size_t)(b*4+hh))*256;
  atomicAdd(&gram[c*16+d], acc);

  // last-block-done: fold softmax(attn) through proj weights into g_W2
  __threadfence();
  __shared__ unsigned int s_done;
  if (tid==0) s_done = atomicAdd(&g_cnt[sc*BB*4 + b*4 + hh], 1u);
  __syncthreads();
  if (s_done != gridDim.x - 1) return;

  const float* norms = g_norms + sc*BB*128 + b*128;
  __shared__ float at[16][17];
  float nq = fmaxf(sqrtf(norms[hh*16+c]), 1e-12f);
  float nk = fmaxf(sqrtf(norms[64+hh*16+d]), 1e-12f);
  float gv;
  asm("ld.global.cg.f32 %0, [%1];" : "=f"(gv) : "l"(&gram[c*16+d]));
  at[c][d] = gv / (nq*nk) * temp[hh];
  __syncthreads();
  if (tid < 16){
    float m = -1e30f;
    #pragma unroll
    for (int j=0;j<16;j++) m = fmaxf(m, at[tid][j]);
    float s = 0.f;
    #pragma unroll
    for (int j=0;j<16;j++){ float e = __expf(at[tid][j]-m); at[tid][j]=e; s+=e; }
    float inv = 1.f/s;
    #pragma unroll
    for (int j=0;j<16;j++) at[tid][j] *= inv;
  }
  __syncthreads();
  float* W2 = g_W2 + (size_t)sc*BB*4096 + (size_t)b*4096;
  #pragma unroll
  for (int r=0;r<4;r++){
    int lin = tid*4 + r;
    int o = lin >> 4, dd = lin & 15;
    float s = 0.f;
    #pragma unroll
    for (int ci=0;ci<16;ci++) s += pw[o*64 + hh*16 + ci]*at[ci][dd];
    W2[o*64 + hh*16 + dd] = s;
  }
}

// ---------------- bilinear sample (half-pixel, edge clamp == jax.image.resize)
__device__ __forceinline__ float bil(const float* __restrict__ ip, int hin, int oy, int ox){
  float r = (float)hin / (float)HH;
  float sy = (oy + 0.5f)*r - 0.5f;
  float sxx = (ox + 0.5f)*r - 0.5f;
  int y0 = (int)floorf(sy), x0 = (int)floorf(sxx);
  float fy = sy - y0, fx = sxx - x0;
  int y0c = min(max(y0,0), hin-1), y1c = min(max(y0+1,0), hin-1);
  int x0c = min(max(x0,0), hin-1), x1c = min(max(x0+1,0), hin-1);
  return (1.f-fy)*((1.f-fx)*ip[y0c*hin+x0c] + fx*ip[y0c*hin+x1c])
       +      fy *((1.f-fx)*ip[y1c*hin+x0c] + fx*ip[y1c*hin+x1c]);
}

// ---------------- xre += up(y1) + up(y2); also zero gn accumulators
__global__ void k_upadd(){
  int i = blockIdx.x*256 + threadIdx.x;
  if (blockIdx.x==0 && threadIdx.x < 32){
    if (threadIdx.x < 16) g_gnsum[threadIdx.x] = 0.f;
    else                  g_gnsq[threadIdx.x-16] = 0.f;
  }
  if (i >= BB*CC*N0) return;
  int p = i % N0; int bc = i / N0;
  int oy = p / WW, ox = p % WW;
  float v = bil(g_y1 + (size_t)bc*N1, 48, oy, ox)
          + bil(g_y2 + (size_t)bc*N2, 24, oy, ox);
  g_xre[i] += v;
}

// ---------------- mamba: one warp per pixel-sequence (lane = d_inner channel)
// also accumulates GroupNorm sum/sumsq (group == t, since c = t*16+lane)
__global__ void __launch_bounds__(256) k_mamba(
    const float* __restrict__ in_w, const float* __restrict__ conv_w, const float* __restrict__ conv_b,
    const float* __restrict__ xproj_w, const float* __restrict__ dtw_g, const float* __restrict__ dtb_g,
    const float* __restrict__ Alog, const float* __restrict__ Dg, const float* __restrict__ out_w)
{
  __shared__ float s_inw[1024];   // (64,16)
  __shared__ float s_xpw[1056];   // (33,32)
  __shared__ float s_cw[128];     // (32,4)
  __shared__ float s_cb[32], s_dtw[32], s_dtb[32], s_D[32];
  __shared__ float s_A[512];      // -exp(Alog)  (32,16)
  __shared__ float s_outw[512];   // (16,32)
  __shared__ float s_stage[8][128];
  __shared__ float s_gs[4], s_gq[4];
  int tid = threadIdx.x;
  for (int i=tid;i<1024;i+=256) s_inw[i]=in_w[i];
  for (int i=tid;i<1056;i+=256) s_xpw[i]=xproj_w[i];
  for (int i=tid;i<128;i+=256)  s_cw[i]=conv_w[i];
  if (tid<32){ s_cb[tid]=conv_b[tid]; s_dtw[tid]=dtw_g[tid]; s_dtb[tid]=dtb_g[tid]; s_D[tid]=Dg[tid]; }
  if (tid<4){ s_gs[tid]=0.f; s_gq[tid]=0.f; }
  for (int i=tid;i<512;i+=256){ s_A[i] = -expf(Alog[i]); s_outw[i]=out_w[i]; }
  __syncthreads();

  int warp = tid >> 5, lane = tid & 31;
  int nseq = blockIdx.x*8 + warp;               // 0..36863
  int b = nseq / N0, p = nseq - b*N0;
  const float* src = g_xre + (size_t)b*64*N0 + p;
  float* stg = s_stage[warp];

  stg[lane]      = src[(size_t)lane*N0];
  stg[32 + lane] = src[(size_t)(32+lane)*N0];
  __syncwarp();

  float xi[4], zz[4];
  #pragma unroll
  for (int t=0;t<4;t++){
    float a = 0.f, c2 = 0.f;
    #pragma unroll
    for (int g=0; g<16; g++){
      float xv = stg[t*16+g];
      a  += xv * s_inw[lane*16+g];
      c2 += xv * s_inw[(32+lane)*16+g];
    }
    xi[t]=a; zz[t]=c2;
  }
  float u[4];
  #pragma unroll
  for (int t=0;t<4;t++){
    float acc = s_cb[lane];
    #pragma unroll
    for (int k=0;k<4;k++){
      int j = t + k - 3;
      if (j >= 0) acc += xi[j]*s_cw[lane*4+k];
    }
    u[t] = siluf(acc);
  }
  __syncwarp();
  #pragma unroll
  for (int t=0;t<4;t++) stg[t*32+lane] = u[t];
  __syncwarp();
  float dtr[4], bc[4];
  #pragma unroll
  for (int t=0;t<4;t++){
    float dr = 0.f, bv = 0.f;
    #pragma unroll
    for (int dd=0; dd<32; dd++){
      float uv = stg[t*32+dd];
      dr += uv * s_xpw[dd];
      bv += uv * s_xpw[(1+lane)*32 + dd];
    }
    dtr[t]=dr; bc[t]=bv;
  }
  float dt[4];
  #pragma unroll
  for (int t=0;t<4;t++){
    float si = dtr[t]*s_dtw[lane] + s_dtb[lane];
    dt[t] = (si > 20.f) ? si : __logf(1.f + __expf(si));
  }
  __syncwarp();
  #pragma unroll
  for (int t=0;t<4;t++) stg[t*32+lane] = bc[t];
  __syncwarp();

  float hs[16];
  #pragma unroll
  for (int s=0;s<16;s++) hs[s]=0.f;
  float y[4];
  #pragma unroll
  for (int t=0;t<4;t++){
    float du = dt[t]*u[t];
    float yt = 0.f;
    #pragma unroll
    for (int s=0;s<16;s++){
      float dA = __expf(dt[t]*s_A[lane*16+s]);
      hs[s] = dA*hs[s] + du*stg[t*32+s];
      yt += hs[s]*stg[t*32+16+s];
    }
    y[t] = (yt + u[t]*s_D[lane]) * siluf(zz[t]);
  }
  __syncwarp();
  #pragma unroll
  for (int t=0;t<4;t++) stg[t*32+lane] = y[t];
  __syncwarp();

  float gs[4], gq[4];
  if (lane < 16){
    float* dst = g_xr + (size_t)b*64*N0 + p;
    #pragma unroll
    for (int t=0;t<4;t++){
      float acc = 0.f;
      #pragma unroll
      for (int dd=0; dd<32; dd++) acc += stg[t*32+dd]*s_outw[lane*32+dd];
      dst[(size_t)(t*16+lane)*N0] = acc;
      gs[t] = acc; gq[t] = acc*acc;
    }
  } else {
    #pragma unroll
    for (int t=0;t<4;t++){ gs[t]=0.f; gq[t]=0.f; }
  }
  #pragma unroll
  for (int t=0;t<4;t++){
    #pragma unroll
    for (int off=16; off; off>>=1){
      gs[t] += __shfl_down_sync(0xffffffffu, gs[t], off);
      gq[t] += __shfl_down_sync(0xffffffffu, gq[t], off);
    }
    if (lane==0){ atomicAdd(&s_gs[t], gs[t]); atomicAdd(&s_gq[t], gq[t]); }
  }
  __syncthreads();
  if (tid < 4){
    atomicAdd(&g_gnsum[b*4+tid], s_gs[tid]);
    atomicAdd(&g_gnsq[b*4+tid],  s_gq[tid]);
  }
}

// ---------------- groupnorm apply + silu + residual (stats from atomics)
__global__ void k_gnout(const float* __restrict__ x, const float* __restrict__ gw,
                        const float* __restrict__ gb, float* __restrict__ out)
{
  int i = blockIdx.x*256 + threadIdx.x;
  if (i >= BB*CC*N0) return;
  int c = (i / N0) % 64;
  int b = i / (64*N0);
  int bg = b*4 + (c>>4);
  float cnt = 16.f*N0;
  float mean = g_gnsum[bg]/cnt;
  float var  = g_gnsq[bg]/cnt - mean*mean;
  float inv  = rsqrtf(var + 1e-5f);
  float v = (g_xr[i]-mean)*inv*gw[c] + gb[c];
  out[i] = siluf(v) + x[i];
}

// ---------------- host ----------------
extern "C" void kernel_launch(void* const* d_in, const int* in_sizes, int n_in,
                              void* d_out, int out_size)
{
  (void)in_sizes; (void)n_in; (void)out_size;
  const float* x        = (const float*)d_in[0];
  const float* qkv_w    = (const float*)d_in[1];
  const float* qkv_b    = (const float*)d_in[2];
  const float* dw_w     = (const float*)d_in[3];
  const float* dw_b     = (const float*)d_in[4];
  const float* po_w     = (const float*)d_in[5];
  const float* po_b     = (const float*)d_in[6];
  const float* temp     = (const float*)d_in[7];
  const float* prca_w   = (const float*)d_in[8];
  const float* prca_b   = (const float*)d_in[9];
  const float* in_w     = (const float*)d_in[10];
  const float* conv_w   = (const float*)d_in[11];
  const float* conv_b   = (const float*)d_in[12];
  const float* xproj_w  = (const float*)d_in[13];
  const float* dtproj_w = (const float*)d_in[14];
  const float* dtproj_b = (const float*)d_in[15];
  const float* Alog     = (const float*)d_in[16];
  const float* Dp       = (const float*)d_in[17];
  const float* out_w    = (const float*)d_in[18];
  const float* gn_w     = (const float*)d_in[19];
  const float* gn_b     = (const float*)d_in[20];
  float* out = (float*)d_out;

  static cudaStream_t st1 = nullptr, st2 = nullptr;
  static cudaEvent_t evF = nullptr, ev1 = nullptr, ev2 = nullptr;
  if (!st1){
    cudaStreamCreateWithFlags(&st1, cudaStreamNonBlocking);
    cudaStreamCreateWithFlags(&st2, cudaStreamNonBlocking);
    cudaEventCreateWithFlags(&evF, cudaEventDisableTiming);
    cudaEventCreateWithFlags(&ev1, cudaEventDisableTiming);
    cudaEventCreateWithFlags(&ev2, cudaEventDisableTiming);
  }

  const int scH[3]   = {96, 48, 24};
  const s64t qoffs[3] = {0, Q0, Q0+Q1};

  k_xp<<<(BB*CC*N0+255)/256, 256>>>(x);
  cudaEventRecord(evF, 0);
  cudaStreamWaitEvent(st1, evF, 0);
  cudaStreamWaitEvent(st2, evF, 0);
  k_pool<<<(BB*CC*N1+255)/256, 256, 0, st1>>>(1, 2, 48, BB*CC*N1);
  k_pool<<<(BB*CC*N2+255)/256, 256, 0, st2>>>(2, 4, 24, BB*CC*N2);

  // per-scale attention chains (independent -> 3 streams)
  for (int s=0; s<3; s++){
    cudaStream_t st = (s==0) ? (cudaStream_t)0 : (s==1 ? st1 : st2);
    int hs = scH[s];
    int n = hs*hs;
    s64t qoff = qoffs[s];
    for (int j=0; j<3; j++){
      int i = 3*s + j;
      if (s < 2)
        k_gemm<128><<<dim3(n/128, 3, BB), 256, 0, st>>>(s, 0LL, 64, 0,
            qkv_w + (size_t)i*192*64, -1, 64, qkv_b + i*192, 6, qoff, n, s);
      else
        k_gemm<64><<<dim3(n/64, 3, BB), 256, 0, st>>>(s, 0LL, 64, 0,
            qkv_w + (size_t)i*192*64, -1, 64, qkv_b + i*192, 6, qoff, n, s);
      k_dwconv<<<dim3((n+255)/256, 192, BB), 256, 0, st>>>(
          dw_w + (size_t)i*192*9, dw_b + i*192, hs, hs, qoff, s);
      k_gram<<<dim3((n+2303)/2304, 4, BB), 256, 0, st>>>(
          n, qoff, s, temp + i*4, po_w + (size_t)i*4096);
      if (s < 2)
        k_gemm<128><<<dim3(n/128, 1, BB), 256, 0, st>>>(3, qoff, 192, 128,
            nullptr, s, 64, po_b + i*64, s, 0LL, n, -1);
      else
        k_gemm<64><<<dim3(n/64, 1, BB), 256, 0, st>>>(3, qoff, 192, 128,
            nullptr, s, 64, po_b + i*64, s, 0LL, n, -1);
    }
  }

  // prca with upsample folded through the linear map
  k_gemm<128><<<dim3(N0/128, 1, BB), 256>>>(0, 0LL, 64, 0, prca_w,       -1, 192, prca_b, 7, 0LL, N0, -1);
  k_gemm<128><<<dim3(N1/128, 1, BB), 256, 0, st1>>>(1, 0LL, 64, 0, prca_w + 64,  -1, 192, nullptr, 4, 0LL, N1, -1);
  cudaEventRecord(ev1, st1);
  k_gemm<64> <<<dim3(N2/64,  1, BB), 256, 0, st2>>>(2, 0LL, 64, 0, prca_w + 128, -1, 192, nullptr, 5, 0LL, N2, -1);
  cudaEventRecord(ev2, st2);
  cudaStreamWaitEvent(0, ev1, 0);
  cudaStreamWaitEvent(0, ev2, 0);
  k_upadd<<<(BB*CC*N0+255)/256, 256>>>();

  k_mamba<<<4608, 256>>>(in_w, conv_w, conv_b, xproj_w, dtproj_w, dtproj_b, Alog, Dp, out_w);
  k_gnout<<<(BB*CC*N0+255)/256, 256>>>(x, gn_w, gn_b, out);
}